// round 3
// baseline (speedup 1.0000x reference)
#include <cuda_runtime.h>

// Shapes (fixed by reference):
//   article: [256, 2048, 300] f32  (d_in[0])
//   options: [256,   64, 300] f32  (d_in[1])
//   out:     [256, 600]       f32  = concat(mean(article,1), mean(options,1))

#define BATCH 256
#define WA    2048
#define WO    64
#define DIM   300
#define NV4   (DIM / 4)     // 75 float4 per feature row (rows are 16B-aligned)
#define SPLIT 16
#define CHUNK (WA / SPLIT)  // 128 words per article partial block

// Deterministic scratch (4.9 MB) + per-batch arrival counters (zero-init,
// reset by last block each call -> graph-replay safe, no allocations).
__device__ float4 g_scratch[BATCH * SPLIT * NV4];
__device__ int    g_count[BATCH];

// Single fused kernel: grid (BATCH, SPLIT+1), block (75, 4).
//  c in [0,16): sum CHUNK article words -> scratch partial; last arriving
//               block for batch b reduces all 16 partials -> out[b, 0:300].
//  c == 16:     full options mean -> out[b, 300:600] directly.
__global__ void __launch_bounds__(300)
fused_kernel(const float* __restrict__ art, const float* __restrict__ opt,
             float* __restrict__ out) {
    const int b  = blockIdx.x;
    const int c  = blockIdx.y;
    const int tx = threadIdx.x;   // 0..74 -> float4 feature column
    const int ty = threadIdx.y;   // 0..3  -> row interleave phase

    __shared__ float4 red[4][NV4];
    __shared__ int is_last;

    if (c < SPLIT) {
        const float4* __restrict__ p = reinterpret_cast<const float4*>(
            art + ((size_t)b * WA + (size_t)c * CHUNK) * DIM) + tx;

        float4 s = make_float4(0.f, 0.f, 0.f, 0.f);
#pragma unroll 8
        for (int w = ty; w < CHUNK; w += 4) {
            float4 v = p[(size_t)w * NV4];
            s.x += v.x; s.y += v.y; s.z += v.z; s.w += v.w;
        }
        red[ty][tx] = s;
        __syncthreads();
        if (ty == 0) {
            float4 a = red[0][tx], b4 = red[1][tx], c4 = red[2][tx], d4 = red[3][tx];
            s.x = a.x + b4.x + c4.x + d4.x;
            s.y = a.y + b4.y + c4.y + d4.y;
            s.z = a.z + b4.z + c4.z + d4.z;
            s.w = a.w + b4.w + c4.w + d4.w;
            g_scratch[((size_t)b * SPLIT + c) * NV4 + tx] = s;
            __threadfence();   // release partial before arrival bump
        }
        __syncthreads();
        if (tx == 0 && ty == 0) {
            int old = atomicAdd(&g_count[b], 1);
            is_last = (old == SPLIT - 1);
        }
        __syncthreads();

        if (is_last) {
            __threadfence();   // acquire: observe all partials
            // ty splits the 16 partials 4-ways; fixed order -> deterministic.
            float4 t = make_float4(0.f, 0.f, 0.f, 0.f);
#pragma unroll
            for (int k = ty; k < SPLIT; k += 4) {
                float4 v = g_scratch[((size_t)b * SPLIT + k) * NV4 + tx];
                t.x += v.x; t.y += v.y; t.z += v.z; t.w += v.w;
            }
            red[ty][tx] = t;
            __syncthreads();
            if (ty == 0) {
                float4 a = red[0][tx], b4 = red[1][tx], c4 = red[2][tx], d4 = red[3][tx];
                const float inv = 1.0f / (float)WA;
                t.x = (a.x + b4.x + c4.x + d4.x) * inv;
                t.y = (a.y + b4.y + c4.y + d4.y) * inv;
                t.z = (a.z + b4.z + c4.z + d4.z) * inv;
                t.w = (a.w + b4.w + c4.w + d4.w) * inv;
                reinterpret_cast<float4*>(out + (size_t)b * (2 * DIM))[tx] = t;
            }
            if (tx == 0 && ty == 0) g_count[b] = 0;   // reset for next replay
        }
    } else {
        // Options: 64 words, full mean, direct store.
        const float4* __restrict__ p = reinterpret_cast<const float4*>(
            opt + (size_t)b * WO * DIM) + tx;

        float4 s = make_float4(0.f, 0.f, 0.f, 0.f);
#pragma unroll 8
        for (int w = ty; w < WO; w += 4) {
            float4 v = p[(size_t)w * NV4];
            s.x += v.x; s.y += v.y; s.z += v.z; s.w += v.w;
        }
        red[ty][tx] = s;
        __syncthreads();
        if (ty == 0) {
            float4 a = red[0][tx], b4 = red[1][tx], c4 = red[2][tx], d4 = red[3][tx];
            const float inv = 1.0f / (float)WO;
            s.x = (a.x + b4.x + c4.x + d4.x) * inv;
            s.y = (a.y + b4.y + c4.y + d4.y) * inv;
            s.z = (a.z + b4.z + c4.z + d4.z) * inv;
            s.w = (a.w + b4.w + c4.w + d4.w) * inv;
            reinterpret_cast<float4*>(out + (size_t)b * (2 * DIM) + DIM)[tx] = s;
        }
    }
}

extern "C" void kernel_launch(void* const* d_in, const int* in_sizes, int n_in,
                              void* d_out, int out_size) {
    const float* article = (const float*)d_in[0];
    const float* options = (const float*)d_in[1];
    float* out = (float*)d_out;

    dim3 block(NV4, 4);            // 300 threads
    dim3 grid(BATCH, SPLIT + 1);   // 4096 article partials + 256 options blocks
    fused_kernel<<<grid, block>>>(article, options, out);
}

// round 4
// speedup vs baseline: 1.0203x; 1.0203x over previous
#include <cuda_runtime.h>

// Shapes (fixed by reference):
//   article: [256, 2048, 300] f32  (d_in[0])
//   options: [256,   64, 300] f32  (d_in[1])
//   out:     [256, 600]       f32  = concat(mean(article,1), mean(options,1))

#define BATCH 256
#define WA    2048
#define WO    64
#define DIM   300
#define NV4   (DIM / 4)       // 75 float4 per feature row
#define SPLIT 16
#define CHUNK (WA / SPLIT)    // 128 words per article partial block
#define CHUNK_F4 (CHUNK * NV4)  // 9600 float4 per chunk
#define OPT_F4   (WO * NV4)     // 4800 float4 per options batch
#define NTHREADS 300

// Deterministic scratch (4.9 MB) + per-batch arrival counters (zero-init,
// reset by the last block each call -> graph-replay safe, no allocations).
__device__ float4 g_scratch[BATCH * SPLIT * NV4];
__device__ int    g_count[BATCH];

// Single fused kernel: grid (BATCH, SPLIT+1), block 300 linear threads.
// Flat access trick: within a chunk, float4 j's feature column is (j mod 75);
// thread tid reads j = i*300 + tid, and since 300 % 75 == 0, it always hits
// column tid%75 -> register accumulation, with every warp request 32B sector-
// aligned (no row-pitch misalignment waste).
__global__ void __launch_bounds__(NTHREADS)
fused_kernel(const float* __restrict__ art, const float* __restrict__ opt,
             float* __restrict__ out) {
    const int b   = blockIdx.x;
    const int c   = blockIdx.y;
    const int tid = threadIdx.x;        // 0..299
    const int col = tid % NV4;          // 0..74  feature float4 column
    const int ph  = tid / NV4;          // 0..3   phase

    __shared__ float4 red[4][NV4];
    __shared__ int is_last;

    if (c < SPLIT) {
        const float4* __restrict__ p = reinterpret_cast<const float4*>(
            art + ((size_t)b * WA + (size_t)c * CHUNK) * DIM);

        float4 s = make_float4(0.f, 0.f, 0.f, 0.f);
#pragma unroll 8
        for (int i = 0; i < CHUNK_F4 / NTHREADS; ++i) {   // 32 iters
            float4 v = p[i * NTHREADS + tid];
            s.x += v.x; s.y += v.y; s.z += v.z; s.w += v.w;
        }
        red[ph][col] = s;
        __syncthreads();
        if (ph == 0) {
            float4 a = red[0][col], b4 = red[1][col], c4 = red[2][col], d4 = red[3][col];
            s.x = a.x + b4.x + c4.x + d4.x;
            s.y = a.y + b4.y + c4.y + d4.y;
            s.z = a.z + b4.z + c4.z + d4.z;
            s.w = a.w + b4.w + c4.w + d4.w;
            g_scratch[((size_t)b * SPLIT + c) * NV4 + col] = s;
            __threadfence();   // release partial before arrival bump
        }
        __syncthreads();
        if (tid == 0) {
            int old = atomicAdd(&g_count[b], 1);
            is_last = (old == SPLIT - 1);
        }
        __syncthreads();

        if (is_last) {
            __threadfence();   // acquire: observe all partials
            float4 t = make_float4(0.f, 0.f, 0.f, 0.f);
#pragma unroll
            for (int k = ph; k < SPLIT; k += 4) {   // fixed order -> deterministic
                float4 v = g_scratch[((size_t)b * SPLIT + k) * NV4 + col];
                t.x += v.x; t.y += v.y; t.z += v.z; t.w += v.w;
            }
            red[ph][col] = t;
            __syncthreads();
            if (ph == 0) {
                float4 a = red[0][col], b4 = red[1][col], c4 = red[2][col], d4 = red[3][col];
                const float inv = 1.0f / (float)WA;
                t.x = (a.x + b4.x + c4.x + d4.x) * inv;
                t.y = (a.y + b4.y + c4.y + d4.y) * inv;
                t.z = (a.z + b4.z + c4.z + d4.z) * inv;
                t.w = (a.w + b4.w + c4.w + d4.w) * inv;
                reinterpret_cast<float4*>(out + (size_t)b * (2 * DIM))[col] = t;
            }
            if (tid == 0) g_count[b] = 0;   // reset for next graph replay
        }
    } else {
        // Options: 64 words, full mean, direct store. Same flat scheme.
        const float4* __restrict__ p = reinterpret_cast<const float4*>(
            opt + (size_t)b * WO * DIM);

        float4 s = make_float4(0.f, 0.f, 0.f, 0.f);
#pragma unroll 8
        for (int i = 0; i < OPT_F4 / NTHREADS; ++i) {     // 16 iters
            float4 v = p[i * NTHREADS + tid];
            s.x += v.x; s.y += v.y; s.z += v.z; s.w += v.w;
        }
        red[ph][col] = s;
        __syncthreads();
        if (ph == 0) {
            float4 a = red[0][col], b4 = red[1][col], c4 = red[2][col], d4 = red[3][col];
            const float inv = 1.0f / (float)WO;
            s.x = (a.x + b4.x + c4.x + d4.x) * inv;
            s.y = (a.y + b4.y + c4.y + d4.y) * inv;
            s.z = (a.z + b4.z + c4.z + d4.z) * inv;
            s.w = (a.w + b4.w + c4.w + d4.w) * inv;
            reinterpret_cast<float4*>(out + (size_t)b * (2 * DIM) + DIM)[col] = s;
        }
    }
}

extern "C" void kernel_launch(void* const* d_in, const int* in_sizes, int n_in,
                              void* d_out, int out_size) {
    const float* article = (const float*)d_in[0];
    const float* options = (const float*)d_in[1];
    float* out = (float*)d_out;

    dim3 grid(BATCH, SPLIT + 1);   // 4096 article partials + 256 options blocks
    fused_kernel<<<grid, NTHREADS>>>(article, options, out);
}

// round 5
// speedup vs baseline: 1.0252x; 1.0048x over previous
#include <cuda_runtime.h>

// Shapes (fixed by reference):
//   article: [256, 2048, 300] f32  (d_in[0])
//   options: [256,   64, 300] f32  (d_in[1])
//   out:     [256, 600]       f32  = concat(mean(article,1), mean(options,1))

#define BATCH 256
#define WA    2048
#define WO    64
#define DIM   300
#define NV4   (DIM / 4)         // 75 float4 per feature row
#define SPLIT 32
#define CHUNK (WA / SPLIT)      // 64 words per article partial block
#define CHUNK_F4 (CHUNK * NV4)  // 4800 float4 per chunk
#define OPT_F4   (WO * NV4)     // 4800 float4 per options batch
#define NTHREADS 300

// Deterministic scratch (9.8 MB, L2-resident) + per-batch arrival counters
// (zero-init, reset by the last block each call -> graph-replay safe).
__device__ float4 g_scratch[BATCH * SPLIT * NV4];
__device__ int    g_count[BATCH];

__device__ __forceinline__ float4 ldcs4(const float4* p) {
    return __ldcs(p);   // evict-first streaming load: keep L2 for scratch
}

// Single fused kernel: grid (BATCH, SPLIT+1), block 300 linear threads.
// Flat access: thread tid reads j = i*300 + tid; 300 % 75 == 0 so tid always
// owns feature column tid%75 (register accumulation), and every warp request
// is 32B sector-aligned.
__global__ void __launch_bounds__(NTHREADS)
fused_kernel(const float* __restrict__ art, const float* __restrict__ opt,
             float* __restrict__ out) {
    const int b   = blockIdx.x;
    const int c   = blockIdx.y;
    const int tid = threadIdx.x;        // 0..299
    const int col = tid % NV4;          // 0..74  feature float4 column
    const int ph  = tid / NV4;          // 0..3   phase

    __shared__ float4 red[4][NV4];
    __shared__ int is_last;

    if (c < SPLIT) {
        const float4* __restrict__ p = reinterpret_cast<const float4*>(
            art + ((size_t)b * WA + (size_t)c * CHUNK) * DIM);

        float4 s = make_float4(0.f, 0.f, 0.f, 0.f);
#pragma unroll 8
        for (int i = 0; i < CHUNK_F4 / NTHREADS; ++i) {   // 16 iters
            float4 v = ldcs4(p + i * NTHREADS + tid);
            s.x += v.x; s.y += v.y; s.z += v.z; s.w += v.w;
        }
        red[ph][col] = s;
        __syncthreads();
        if (ph == 0) {
            float4 a = red[0][col], b4 = red[1][col], c4 = red[2][col], d4 = red[3][col];
            s.x = a.x + b4.x + c4.x + d4.x;
            s.y = a.y + b4.y + c4.y + d4.y;
            s.z = a.z + b4.z + c4.z + d4.z;
            s.w = a.w + b4.w + c4.w + d4.w;
            g_scratch[((size_t)b * SPLIT + c) * NV4 + col] = s;
            __threadfence();   // release partial before arrival bump
        }
        __syncthreads();
        if (tid == 0) {
            int old = atomicAdd(&g_count[b], 1);
            is_last = (old == SPLIT - 1);
        }
        __syncthreads();

        if (is_last) {
            __threadfence();   // acquire: observe all partials
            float4 t = make_float4(0.f, 0.f, 0.f, 0.f);
#pragma unroll
            for (int k = ph; k < SPLIT; k += 4) {   // fixed order -> deterministic
                float4 v = g_scratch[((size_t)b * SPLIT + k) * NV4 + col];
                t.x += v.x; t.y += v.y; t.z += v.z; t.w += v.w;
            }
            red[ph][col] = t;
            __syncthreads();
            if (ph == 0) {
                float4 a = red[0][col], b4 = red[1][col], c4 = red[2][col], d4 = red[3][col];
                const float inv = 1.0f / (float)WA;
                t.x = (a.x + b4.x + c4.x + d4.x) * inv;
                t.y = (a.y + b4.y + c4.y + d4.y) * inv;
                t.z = (a.z + b4.z + c4.z + d4.z) * inv;
                t.w = (a.w + b4.w + c4.w + d4.w) * inv;
                reinterpret_cast<float4*>(out + (size_t)b * (2 * DIM))[col] = t;
            }
            if (tid == 0) g_count[b] = 0;   // reset for next graph replay
        }
    } else {
        // Options: 64 words, full mean, direct store. Same flat scheme.
        const float4* __restrict__ p = reinterpret_cast<const float4*>(
            opt + (size_t)b * WO * DIM);

        float4 s = make_float4(0.f, 0.f, 0.f, 0.f);
#pragma unroll 8
        for (int i = 0; i < OPT_F4 / NTHREADS; ++i) {     // 16 iters
            float4 v = ldcs4(p + i * NTHREADS + tid);
            s.x += v.x; s.y += v.y; s.z += v.z; s.w += v.w;
        }
        red[ph][col] = s;
        __syncthreads();
        if (ph == 0) {
            float4 a = red[0][col], b4 = red[1][col], c4 = red[2][col], d4 = red[3][col];
            const float inv = 1.0f / (float)WO;
            s.x = (a.x + b4.x + c4.x + d4.x) * inv;
            s.y = (a.y + b4.y + c4.y + d4.y) * inv;
            s.z = (a.z + b4.z + c4.z + d4.z) * inv;
            s.w = (a.w + b4.w + c4.w + d4.w) * inv;
            reinterpret_cast<float4*>(out + (size_t)b * (2 * DIM) + DIM)[col] = s;
        }
    }
}

extern "C" void kernel_launch(void* const* d_in, const int* in_sizes, int n_in,
                              void* d_out, int out_size) {
    const float* article = (const float*)d_in[0];
    const float* options = (const float*)d_in[1];
    float* out = (float*)d_out;

    dim3 grid(BATCH, SPLIT + 1);   // 8192 article partials + 256 options blocks
    fused_kernel<<<grid, NTHREADS>>>(article, options, out);
}